// round 9
// baseline (speedup 1.0000x reference)
#include <cuda_runtime.h>
#include <cuda_bf16.h>

// Problem constants (fixed by the reference).
#define BN 4096
#define DN 768
#define KN 60
#define NLOGITS 61   // [pos, 60 negs]

// Scratch (__device__ globals: no allocation allowed).
__device__ __nv_bfloat16 g_item_bf16[BN * DN];   // 6.3 MB bf16 mirror of item table
__device__ float g_row_loss[BN];
__device__ int   g_ctr = 0;

// ---------------------------------------------------------------------------
// Prologue: fp32 item table -> bf16 mirror. 8 floats per thread.
// ---------------------------------------------------------------------------
__global__ void __launch_bounds__(256)
convert_items_kernel(const float* __restrict__ item_emb)
{
    const int i = blockIdx.x * blockDim.x + threadIdx.x;   // 0 .. BN*DN/8-1
    const float4* src = reinterpret_cast<const float4*>(item_emb);
    const float4 a = src[2 * i];
    const float4 b = src[2 * i + 1];

    __nv_bfloat162 r[4];
    r[0] = __floats2bfloat162_rn(a.x, a.y);
    r[1] = __floats2bfloat162_rn(a.z, a.w);
    r[2] = __floats2bfloat162_rn(b.x, b.y);
    r[3] = __floats2bfloat162_rn(b.z, b.w);
    reinterpret_cast<uint4*>(g_item_bf16)[i] = *reinterpret_cast<uint4*>(r);
}

// 8 bf16 (uint4) dot fp32x8 (two float4) accumulated into fp32.
__device__ __forceinline__ void dot8(float& acc, const uint4& pv,
                                     const float4& uv0, const float4& uv1)
{
    const float2 f0 = __bfloat1622float2(*reinterpret_cast<const __nv_bfloat162*>(&pv.x));
    const float2 f1 = __bfloat1622float2(*reinterpret_cast<const __nv_bfloat162*>(&pv.y));
    const float2 f2 = __bfloat1622float2(*reinterpret_cast<const __nv_bfloat162*>(&pv.z));
    const float2 f3 = __bfloat1622float2(*reinterpret_cast<const __nv_bfloat162*>(&pv.w));
    acc = fmaf(f0.x, uv0.x, acc);
    acc = fmaf(f0.y, uv0.y, acc);
    acc = fmaf(f1.x, uv0.z, acc);
    acc = fmaf(f1.y, uv0.w, acc);
    acc = fmaf(f2.x, uv1.x, acc);
    acc = fmaf(f2.y, uv1.y, acc);
    acc = fmaf(f3.x, uv1.z, acc);
    acc = fmaf(f3.y, uv1.w, acc);
}

// ---------------------------------------------------------------------------
// Main: one CTA per user row; 8 warps split the 61 logits.
// User row in REGISTERS; two logits/iter (MLP=6); paired 6-shfl reduction;
// 4 CTAs/SM (64-reg cap) for ~66% occupancy.
// ---------------------------------------------------------------------------
__global__ void __launch_bounds__(256, 4)
u2i_loss_kernel(const float* __restrict__ user_emb,
                const int*   __restrict__ neg_idx,
                float*       __restrict__ out)
{
    __shared__ float su[DN];
    __shared__ float slog[64];        // 61 used, rest padded with -inf
    __shared__ int   s_last;

    const int b    = blockIdx.x;
    const int tid  = threadIdx.x;
    const int warp = tid >> 5;
    const int lane = tid & 31;

    // Stage user row coalesced into smem once, then lift this lane's slice
    // into registers (6 x float4 = 24 regs).
    const float4* u4  = reinterpret_cast<const float4*>(user_emb + (size_t)b * DN);
    float4*       su4 = reinterpret_cast<float4*>(su);
    if (tid < DN / 4) su4[tid] = u4[tid];
    if (tid >= 61 && tid < 64) slog[tid] = -3.0e38f;
    __syncthreads();

    float4 uv[6];
    #pragma unroll
    for (int t = 0; t < 3; ++t) {
        uv[2 * t]     = su4[2 * (t * 32 + lane)];
        uv[2 * t + 1] = su4[2 * (t * 32 + lane) + 1];
    }

    // Logit pairs (j, j+8): warps 0-4 do 4 pairs, warps 5-7 do 3 pairs + 1.
    for (int j = warp; j < NLOGITS; j += 16) {
        const int  j2   = j + 8;
        const bool has2 = (j2 < NLOGITS);

        const int it0 = (j == 0) ? b : neg_idx[b * KN + (j - 1)];
        const int it1 = has2 ? neg_idx[b * KN + (j2 - 1)] : it0;

        const uint4* p0 = reinterpret_cast<const uint4*>(g_item_bf16 + (size_t)it0 * DN);
        const uint4* p1 = reinterpret_cast<const uint4*>(g_item_bf16 + (size_t)it1 * DN);

        // Issue all 6 gathers up front (MLP=6).
        uint4 a0 = __ldg(&p0[lane]);
        uint4 a1 = __ldg(&p0[32 + lane]);
        uint4 a2 = __ldg(&p0[64 + lane]);
        uint4 b0 = __ldg(&p1[lane]);
        uint4 b1 = __ldg(&p1[32 + lane]);
        uint4 b2 = __ldg(&p1[64 + lane]);

        float acc0 = 0.0f, acc1 = 0.0f;
        dot8(acc0, a0, uv[0], uv[1]);
        dot8(acc0, a1, uv[2], uv[3]);
        dot8(acc0, a2, uv[4], uv[5]);
        dot8(acc1, b0, uv[0], uv[1]);
        dot8(acc1, b1, uv[2], uv[3]);
        dot8(acc1, b2, uv[4], uv[5]);

        // Paired reduction: 6 shfls for BOTH sums.
        // After xor-16, every lane holds its pair's half-sum for each acc.
        acc0 += __shfl_xor_sync(0xffffffffu, acc0, 16);
        acc1 += __shfl_xor_sync(0xffffffffu, acc1, 16);
        // Lanes 0-15 continue acc0, lanes 16-31 continue acc1.
        float v = (lane < 16) ? acc0 : acc1;
        #pragma unroll
        for (int o = 8; o > 0; o >>= 1)
            v += __shfl_xor_sync(0xffffffffu, v, o);
        // v on lane 0 = full acc0 sum; v on lane 16 = full acc1 sum.
        if (lane == 0) slog[j] = v;
        if (lane == 16 && has2) slog[j2] = v;
    }
    __syncthreads();

    // Warp 0: stable logsumexp over 61 logits (2 per lane).
    if (warp == 0) {
        const float l0 = slog[lane];
        const float l1 = slog[lane + 32];
        float m = fmaxf(l0, l1);
        #pragma unroll
        for (int o = 16; o > 0; o >>= 1)
            m = fmaxf(m, __shfl_xor_sync(0xffffffffu, m, o));
        float s = expf(l0 - m) + ((lane + 32 < NLOGITS) ? expf(l1 - m) : 0.0f);
        #pragma unroll
        for (int o = 16; o > 0; o >>= 1)
            s += __shfl_xor_sync(0xffffffffu, s, o);
        if (lane == 0) {
            g_row_loss[b] = logf(s) + m - slog[0];
            __threadfence();
            const int t = atomicAdd(&g_ctr, 1);
            s_last = (t == BN - 1);
        }
    }
    __syncthreads();

    // Last CTA: deterministic mean over all 4096 row losses.
    if (s_last) {
        __threadfence();
        __shared__ float sred[256];
        float a = 0.0f;
        #pragma unroll
        for (int i = tid; i < BN; i += 256) a += g_row_loss[i];
        sred[tid] = a;
        __syncthreads();
        #pragma unroll
        for (int st = 128; st > 0; st >>= 1) {
            if (tid < st) sred[tid] += sred[tid + st];
            __syncthreads();
        }
        if (tid == 0) {
            out[0] = sred[0] * (1.0f / (float)BN);
            g_ctr = 0;                                 // reset for next graph replay
        }
    }
}

extern "C" void kernel_launch(void* const* d_in, const int* in_sizes, int n_in,
                              void* d_out, int out_size)
{
    const float* user_emb = (const float*)d_in[0];
    const float* item_emb = (const float*)d_in[1];
    const int*   neg_idx  = (const int*)d_in[2];
    float*       out      = (float*)d_out;

    convert_items_kernel<<<BN * DN / 8 / 256, 256>>>(item_emb);
    u2i_loss_kernel<<<BN, 256>>>(user_emb, neg_idx, out);
}

// round 10
// speedup vs baseline: 1.1692x; 1.1692x over previous
#include <cuda_runtime.h>
#include <cuda_fp16.h>

// Problem constants (fixed by the reference).
#define BN 4096
#define DN 768
#define KN 60
#define NLOGITS 61   // [pos, 60 negs]

// Scratch (__device__ globals: no allocation allowed).
__device__ __half g_item_f16[BN * DN];   // 6.3 MB fp16 mirror of item table
__device__ float g_row_loss[BN];
__device__ int   g_ctr = 0;

// ---------------------------------------------------------------------------
// Prologue: fp32 item table -> fp16 mirror. 8 floats per thread.
// ---------------------------------------------------------------------------
__global__ void __launch_bounds__(256)
convert_items_kernel(const float* __restrict__ item_emb)
{
    const int i = blockIdx.x * blockDim.x + threadIdx.x;   // 0 .. BN*DN/8-1
    const float4* src = reinterpret_cast<const float4*>(item_emb);
    const float4 a = src[2 * i];
    const float4 b = src[2 * i + 1];

    __half2 r[4];
    r[0] = __floats2half2_rn(a.x, a.y);
    r[1] = __floats2half2_rn(a.z, a.w);
    r[2] = __floats2half2_rn(b.x, b.y);
    r[3] = __floats2half2_rn(b.z, b.w);
    reinterpret_cast<uint4*>(g_item_f16)[i] = *reinterpret_cast<uint4*>(r);
}

#define H2(x) (*reinterpret_cast<const __half2*>(&(x)))

// One uint4 (8 f16 item values) into two f16x2 accumulators against 4 user h2 regs.
__device__ __forceinline__ void dot8h(__half2& acca, __half2& accb, const uint4& pv,
                                      const __half2& u0, const __half2& u1,
                                      const __half2& u2, const __half2& u3)
{
    acca = __hfma2(H2(pv.x), u0, acca);
    accb = __hfma2(H2(pv.y), u1, accb);
    acca = __hfma2(H2(pv.z), u2, acca);
    accb = __hfma2(H2(pv.w), u3, accb);
}

// ---------------------------------------------------------------------------
// Main: one CTA per user row; 8 warps split the 61 logits.
// User row in 12 f16x2 REGISTERS; two logits/iter (MLP=6); HFMA2 partial
// sums (4 short chains) finished in fp32.
// ---------------------------------------------------------------------------
__global__ void __launch_bounds__(256, 4)
u2i_loss_kernel(const float* __restrict__ user_emb,
                const int*   __restrict__ neg_idx,
                float*       __restrict__ out)
{
    __shared__ float slog[64];        // 61 used, rest padded with -inf
    __shared__ int   s_last;

    const int b    = blockIdx.x;
    const int tid  = threadIdx.x;
    const int warp = tid >> 5;
    const int lane = tid & 31;

    if (tid >= 61 && tid < 64) slog[tid] = -3.0e38f;

    // Each lane loads its 24-float user slice directly (8 warps duplicate ->
    // L1 broadcast hits) and converts to 12 f16x2 regs.
    const float4* u4 = reinterpret_cast<const float4*>(user_emb + (size_t)b * DN);
    __half2 uh[12];
    #pragma unroll
    for (int t = 0; t < 3; ++t) {
        const float4 x = __ldg(&u4[2 * (t * 32 + lane)]);
        const float4 y = __ldg(&u4[2 * (t * 32 + lane) + 1]);
        uh[4 * t + 0] = __floats2half2_rn(x.x, x.y);
        uh[4 * t + 1] = __floats2half2_rn(x.z, x.w);
        uh[4 * t + 2] = __floats2half2_rn(y.x, y.y);
        uh[4 * t + 3] = __floats2half2_rn(y.z, y.w);
    }

    // Logit pairs (j, j+8): warps 0-4 do 4 pairs, warps 5-7 do 3 pairs + 1.
    #pragma unroll
    for (int j = warp; j < NLOGITS; j += 16) {
        const int  j2   = j + 8;
        const bool has2 = (j2 < NLOGITS);

        const int it0 = (j == 0) ? b : neg_idx[b * KN + (j - 1)];
        const int it1 = has2 ? neg_idx[b * KN + (j2 - 1)] : it0;

        const uint4* p0 = reinterpret_cast<const uint4*>(g_item_f16 + (size_t)it0 * DN);
        const uint4* p1 = reinterpret_cast<const uint4*>(g_item_f16 + (size_t)it1 * DN);

        // Issue all 6 gathers up front (MLP=6).
        const uint4 a0 = __ldg(&p0[lane]);
        const uint4 a1 = __ldg(&p0[32 + lane]);
        const uint4 a2 = __ldg(&p0[64 + lane]);
        const uint4 c0 = __ldg(&p1[lane]);
        const uint4 c1 = __ldg(&p1[32 + lane]);
        const uint4 c2 = __ldg(&p1[64 + lane]);

        const __half2 hz = __float2half2_rn(0.0f);
        __half2 s0a = hz, s0b = hz, s1a = hz, s1b = hz;
        dot8h(s0a, s0b, a0, uh[0], uh[1], uh[2],  uh[3]);
        dot8h(s0a, s0b, a1, uh[4], uh[5], uh[6],  uh[7]);
        dot8h(s0a, s0b, a2, uh[8], uh[9], uh[10], uh[11]);
        dot8h(s1a, s1b, c0, uh[0], uh[1], uh[2],  uh[3]);
        dot8h(s1a, s1b, c1, uh[4], uh[5], uh[6],  uh[7]);
        dot8h(s1a, s1b, c2, uh[8], uh[9], uh[10], uh[11]);

        // Finish in fp32.
        const float2 f0a = __half22float2(s0a);
        const float2 f0b = __half22float2(s0b);
        const float2 f1a = __half22float2(s1a);
        const float2 f1b = __half22float2(s1b);
        float acc0 = (f0a.x + f0a.y) + (f0b.x + f0b.y);
        float acc1 = (f1a.x + f1a.y) + (f1b.x + f1b.y);

        // Paired reduction: 6 shfls for BOTH sums.
        acc0 += __shfl_xor_sync(0xffffffffu, acc0, 16);
        acc1 += __shfl_xor_sync(0xffffffffu, acc1, 16);
        float v = (lane < 16) ? acc0 : acc1;
        #pragma unroll
        for (int o = 8; o > 0; o >>= 1)
            v += __shfl_xor_sync(0xffffffffu, v, o);
        if (lane == 0) slog[j] = v;
        if (lane == 16 && has2) slog[j2] = v;
    }
    __syncthreads();

    // Warp 0: stable logsumexp over 61 logits (2 per lane).
    if (warp == 0) {
        const float l0 = slog[lane];
        const float l1 = slog[lane + 32];
        float m = fmaxf(l0, l1);
        #pragma unroll
        for (int o = 16; o > 0; o >>= 1)
            m = fmaxf(m, __shfl_xor_sync(0xffffffffu, m, o));
        float s = expf(l0 - m) + ((lane + 32 < NLOGITS) ? expf(l1 - m) : 0.0f);
        #pragma unroll
        for (int o = 16; o > 0; o >>= 1)
            s += __shfl_xor_sync(0xffffffffu, s, o);
        if (lane == 0) {
            g_row_loss[b] = logf(s) + m - slog[0];
            __threadfence();
            const int t = atomicAdd(&g_ctr, 1);
            s_last = (t == BN - 1);
        }
    }
    __syncthreads();

    // Last CTA: deterministic mean over all 4096 row losses.
    if (s_last) {
        __threadfence();
        __shared__ float sred[256];
        float a = 0.0f;
        #pragma unroll
        for (int i = tid; i < BN; i += 256) a += g_row_loss[i];
        sred[tid] = a;
        __syncthreads();
        #pragma unroll
        for (int st = 128; st > 0; st >>= 1) {
            if (tid < st) sred[tid] += sred[tid + st];
            __syncthreads();
        }
        if (tid == 0) {
            out[0] = sred[0] * (1.0f / (float)BN);
            g_ctr = 0;                                 // reset for next graph replay
        }
    }
}

extern "C" void kernel_launch(void* const* d_in, const int* in_sizes, int n_in,
                              void* d_out, int out_size)
{
    const float* user_emb = (const float*)d_in[0];
    const float* item_emb = (const float*)d_in[1];
    const int*   neg_idx  = (const int*)d_in[2];
    float*       out      = (float*)d_out;

    convert_items_kernel<<<BN * DN / 8 / 256, 256>>>(item_emb);
    u2i_loss_kernel<<<BN, 256>>>(user_emb, neg_idx, out);
}

// round 11
// speedup vs baseline: 1.3722x; 1.1736x over previous
#include <cuda_runtime.h>

// Problem constants (fixed by the reference).
#define BN 4096
#define DN 768
#define KN 60
#define NLOGITS 61   // [pos, 60 negs]
#define NW 192       // int32 words per row (768 int8)

// Scratch (__device__ globals: no allocation allowed).
__device__ int   g_item_i8[BN * NW];    // 3 MB int8 item table (packed int32)
__device__ int   g_user_i8[BN * NW];    // 3 MB int8 user table
__device__ float g_item_scale[BN];      // per-row max/127
__device__ float g_user_scale[BN];
__device__ float g_row_loss[BN];
__device__ int   g_ctr = 0;

// ---------------------------------------------------------------------------
// Prologue: per-row symmetric int8 quantization of BOTH tables.
// One warp per row; gwarp < BN -> item row, else user row.
// Word t*32+lane covers dims [4*(t*32+lane), +4).
// ---------------------------------------------------------------------------
__global__ void __launch_bounds__(256)
quantize_rows_kernel(const float* __restrict__ item_emb,
                     const float* __restrict__ user_emb)
{
    const int gwarp = (blockIdx.x * 256 + threadIdx.x) >> 5;   // 0 .. 2*BN-1
    const int lane  = threadIdx.x & 31;

    const float* src;
    int*   dst;
    float* sc;
    if (gwarp < BN) {
        src = item_emb + (size_t)gwarp * DN;
        dst = g_item_i8 + (size_t)gwarp * NW;
        sc  = &g_item_scale[gwarp];
    } else {
        const int r = gwarp - BN;
        src = user_emb + (size_t)r * DN;
        dst = g_user_i8 + (size_t)r * NW;
        sc  = &g_user_scale[r];
    }

    const float4* s4 = reinterpret_cast<const float4*>(src);
    float4 v[6];
    float m = 0.0f;
    #pragma unroll
    for (int t = 0; t < 6; ++t) {
        v[t] = __ldg(&s4[t * 32 + lane]);
        m = fmaxf(m, fmaxf(fmaxf(fabsf(v[t].x), fabsf(v[t].y)),
                           fmaxf(fabsf(v[t].z), fabsf(v[t].w))));
    }
    #pragma unroll
    for (int o = 16; o > 0; o >>= 1)
        m = fmaxf(m, __shfl_xor_sync(0xffffffffu, m, o));
    m = fmaxf(m, 1e-20f);
    const float inv = 127.0f / m;

    #pragma unroll
    for (int t = 0; t < 6; ++t) {
        const int qx = __float2int_rn(v[t].x * inv);
        const int qy = __float2int_rn(v[t].y * inv);
        const int qz = __float2int_rn(v[t].z * inv);
        const int qw = __float2int_rn(v[t].w * inv);
        dst[t * 32 + lane] = (qx & 0xFF) | ((qy & 0xFF) << 8) |
                             ((qz & 0xFF) << 16) | (qw << 24);
    }
    if (lane == 0) *sc = m / 127.0f;
}

// ---------------------------------------------------------------------------
// Main: one CTA per user row; 8 warps split the 61 logits.
// int8 DP4A dots with exact int32 accumulation; per-row descale at the end.
// Two logits per iteration (MLP=12 x LDG.32).
// ---------------------------------------------------------------------------
__global__ void __launch_bounds__(256, 5)
u2i_loss_kernel(const int* __restrict__ neg_idx,
                float*     __restrict__ out)
{
    __shared__ float slog[64];        // 61 used, rest padded with -inf
    __shared__ int   s_last;

    const int b    = blockIdx.x;
    const int tid  = threadIdx.x;
    const int warp = tid >> 5;
    const int lane = tid & 31;

    if (tid >= 61 && tid < 64) slog[tid] = -3.0e38f;

    // User slice: 6 int32 words + scale.
    const int* uq = g_user_i8 + (size_t)b * NW;
    int u[6];
    #pragma unroll
    for (int t = 0; t < 6; ++t) u[t] = __ldg(&uq[t * 32 + lane]);
    const float su = __ldg(&g_user_scale[b]);

    // Logit pairs (j, j+8): warps 0-4 do 4 pairs, warps 5-7 do 3 pairs + 1.
    for (int j = warp; j < NLOGITS; j += 16) {
        const int  j2   = j + 8;
        const bool has2 = (j2 < NLOGITS);

        const int it0 = (j == 0) ? b : neg_idx[b * KN + (j - 1)];
        const int it1 = has2 ? neg_idx[b * KN + (j2 - 1)] : it0;

        const int* p0 = g_item_i8 + (size_t)it0 * NW;
        const int* p1 = g_item_i8 + (size_t)it1 * NW;

        // Issue all 12 gathers up front (coalesced 128B LDG.32 each).
        int a0[6], a1[6];
        #pragma unroll
        for (int t = 0; t < 6; ++t) a0[t] = __ldg(&p0[t * 32 + lane]);
        #pragma unroll
        for (int t = 0; t < 6; ++t) a1[t] = __ldg(&p1[t * 32 + lane]);

        const float sv0 = __ldg(&g_item_scale[it0]);
        const float sv1 = __ldg(&g_item_scale[it1]);

        int acc0 = 0, acc1 = 0;
        #pragma unroll
        for (int t = 0; t < 6; ++t) acc0 = __dp4a(a0[t], u[t], acc0);
        #pragma unroll
        for (int t = 0; t < 6; ++t) acc1 = __dp4a(a1[t], u[t], acc1);

        // Paired reduction: 6 shfls for BOTH sums (exact int adds).
        acc0 += __shfl_xor_sync(0xffffffffu, acc0, 16);
        acc1 += __shfl_xor_sync(0xffffffffu, acc1, 16);
        int v = (lane < 16) ? acc0 : acc1;
        #pragma unroll
        for (int o = 8; o > 0; o >>= 1)
            v += __shfl_xor_sync(0xffffffffu, v, o);

        if (lane == 0)          slog[j]  = (float)v * su * sv0;
        if (lane == 16 && has2) slog[j2] = (float)v * su * sv1;
    }
    __syncthreads();

    // Warp 0: stable logsumexp over 61 logits (2 per lane).
    if (warp == 0) {
        const float l0 = slog[lane];
        const float l1 = slog[lane + 32];
        float m = fmaxf(l0, l1);
        #pragma unroll
        for (int o = 16; o > 0; o >>= 1)
            m = fmaxf(m, __shfl_xor_sync(0xffffffffu, m, o));
        float s = expf(l0 - m) + ((lane + 32 < NLOGITS) ? expf(l1 - m) : 0.0f);
        #pragma unroll
        for (int o = 16; o > 0; o >>= 1)
            s += __shfl_xor_sync(0xffffffffu, s, o);
        if (lane == 0) {
            g_row_loss[b] = logf(s) + m - slog[0];
            __threadfence();
            const int t = atomicAdd(&g_ctr, 1);
            s_last = (t == BN - 1);
        }
    }
    __syncthreads();

    // Last CTA: deterministic mean over all 4096 row losses.
    if (s_last) {
        __threadfence();
        __shared__ float sred[256];
        float a = 0.0f;
        #pragma unroll
        for (int i = tid; i < BN; i += 256) a += g_row_loss[i];
        sred[tid] = a;
        __syncthreads();
        #pragma unroll
        for (int st = 128; st > 0; st >>= 1) {
            if (tid < st) sred[tid] += sred[tid + st];
            __syncthreads();
        }
        if (tid == 0) {
            out[0] = sred[0] * (1.0f / (float)BN);
            g_ctr = 0;                                 // reset for next graph replay
        }
    }
}

extern "C" void kernel_launch(void* const* d_in, const int* in_sizes, int n_in,
                              void* d_out, int out_size)
{
    const float* user_emb = (const float*)d_in[0];
    const float* item_emb = (const float*)d_in[1];
    const int*   neg_idx  = (const int*)d_in[2];
    float*       out      = (float*)d_out;

    quantize_rows_kernel<<<2 * BN / 8, 256>>>(item_emb, user_emb);
    u2i_loss_kernel<<<BN, 256>>>(neg_idx, out);
}

// round 12
// speedup vs baseline: 1.5294x; 1.1145x over previous
#include <cuda_runtime.h>

// Problem constants (fixed by the reference).
#define BN 4096
#define DN 768
#define KN 60
#define NLOGITS 61   // [pos, 60 negs]
#define NW 192       // int32 words per row (768 int8)

// Scratch (__device__ globals: no allocation allowed).
__device__ int   g_item_i8[BN * NW];    // 3 MB int8 item table (packed int32)
__device__ int   g_user_i8[BN * NW];    // 3 MB int8 user table
__device__ float g_item_scale[BN];      // per-row max/127
__device__ float g_user_scale[BN];
__device__ float g_row_loss[BN];
__device__ int   g_ctr = 0;

// ---------------------------------------------------------------------------
// Prologue: per-row symmetric int8 quantization of BOTH tables.
// One warp per row; gwarp < BN -> item row, else user row.
// ---------------------------------------------------------------------------
__global__ void __launch_bounds__(256)
quantize_rows_kernel(const float* __restrict__ item_emb,
                     const float* __restrict__ user_emb)
{
    const int gwarp = (blockIdx.x * 256 + threadIdx.x) >> 5;   // 0 .. 2*BN-1
    const int lane  = threadIdx.x & 31;

    const float* src;
    int*   dst;
    float* sc;
    if (gwarp < BN) {
        src = item_emb + (size_t)gwarp * DN;
        dst = g_item_i8 + (size_t)gwarp * NW;
        sc  = &g_item_scale[gwarp];
    } else {
        const int r = gwarp - BN;
        src = user_emb + (size_t)r * DN;
        dst = g_user_i8 + (size_t)r * NW;
        sc  = &g_user_scale[r];
    }

    const float4* s4 = reinterpret_cast<const float4*>(src);
    float4 v[6];
    float m = 0.0f;
    #pragma unroll
    for (int t = 0; t < 6; ++t) {
        v[t] = __ldg(&s4[t * 32 + lane]);
        m = fmaxf(m, fmaxf(fmaxf(fabsf(v[t].x), fabsf(v[t].y)),
                           fmaxf(fabsf(v[t].z), fabsf(v[t].w))));
    }
    #pragma unroll
    for (int o = 16; o > 0; o >>= 1)
        m = fmaxf(m, __shfl_xor_sync(0xffffffffu, m, o));
    m = fmaxf(m, 1e-20f);
    const float inv = 127.0f / m;

    #pragma unroll
    for (int t = 0; t < 6; ++t) {
        const int qx = __float2int_rn(v[t].x * inv);
        const int qy = __float2int_rn(v[t].y * inv);
        const int qz = __float2int_rn(v[t].z * inv);
        const int qw = __float2int_rn(v[t].w * inv);
        dst[t * 32 + lane] = (qx & 0xFF) | ((qy & 0xFF) << 8) |
                             ((qz & 0xFF) << 16) | (qw << 24);
    }
    if (lane == 0) *sc = m / 127.0f;
}

__device__ __forceinline__ void load6(int (&r)[6], const int* __restrict__ row, int lane)
{
    #pragma unroll
    for (int t = 0; t < 6; ++t) r[t] = __ldg(&row[t * 32 + lane]);
}

// ---------------------------------------------------------------------------
// Main: one CTA per user row; 8 warps, pair (j, j+8) per iteration, 4 iters.
// Indices + scales prefetched to smem; iterations software-pipelined with a
// register double buffer so gather latency overlaps the dp4a+shfl tail.
// ---------------------------------------------------------------------------
__global__ void __launch_bounds__(256, 5)
u2i_loss_kernel(const int* __restrict__ neg_idx,
                float*     __restrict__ out)
{
    __shared__ int   s_idx[64];
    __shared__ float s_scale[64];
    __shared__ float slog[64];        // 61 used, rest padded with -inf
    __shared__ int   s_last;

    const int b    = blockIdx.x;
    const int tid  = threadIdx.x;
    const int warp = tid >> 5;
    const int lane = tid & 31;

    // Prefetch all logit item indices + scales (one coalesced pass).
    if (tid < 64) {
        const int j  = tid;
        const int it = (j == 0) ? b : ((j < NLOGITS) ? __ldg(&neg_idx[b * KN + j - 1]) : 0);
        s_idx[j]   = it;
        s_scale[j] = __ldg(&g_item_scale[it]);
        if (j >= NLOGITS) slog[j] = -3.0e38f;
    }

    // User slice: 6 int32 words + scale.
    const int* uq = g_user_i8 + (size_t)b * NW;
    int u[6];
    load6(u, uq, lane);
    const float su = __ldg(&g_user_scale[b]);
    __syncthreads();

    // Gather row pointers for all 4 iterations (from smem; cheap).
    const int* p0[4];
    const int* p1[4];
    #pragma unroll
    for (int t = 0; t < 4; ++t) {
        const int j = warp + 16 * t;
        p0[t] = g_item_i8 + (size_t)s_idx[j] * NW;
        p1[t] = g_item_i8 + (size_t)s_idx[j + 8] * NW;   // dummy row 0 if j+8>=61
    }

    // Software pipeline: prefetch t=0, then overlap loads(t+1) with compute(t).
    int a[6], c[6], na[6], nc[6];
    load6(a, p0[0], lane);
    load6(c, p1[0], lane);

    #pragma unroll
    for (int t = 0; t < 4; ++t) {
        if (t < 3) {
            load6(na, p0[t + 1], lane);
            load6(nc, p1[t + 1], lane);
        }

        int acc0 = 0, acc1 = 0;
        #pragma unroll
        for (int k = 0; k < 6; ++k) acc0 = __dp4a(a[k], u[k], acc0);
        #pragma unroll
        for (int k = 0; k < 6; ++k) acc1 = __dp4a(c[k], u[k], acc1);

        // Paired reduction: 6 shfls for BOTH sums (exact int adds).
        acc0 += __shfl_xor_sync(0xffffffffu, acc0, 16);
        acc1 += __shfl_xor_sync(0xffffffffu, acc1, 16);
        int v = (lane < 16) ? acc0 : acc1;
        #pragma unroll
        for (int o = 8; o > 0; o >>= 1)
            v += __shfl_xor_sync(0xffffffffu, v, o);

        const int j  = warp + 16 * t;
        const int j2 = j + 8;
        if (lane == 0)                      slog[j]  = (float)v * su * s_scale[j];
        if (lane == 16 && j2 < NLOGITS)     slog[j2] = (float)v * su * s_scale[j2];

        if (t < 3) {
            #pragma unroll
            for (int k = 0; k < 6; ++k) { a[k] = na[k]; c[k] = nc[k]; }
        }
    }
    __syncthreads();

    // Warp 0: stable logsumexp over 61 logits (2 per lane).
    if (warp == 0) {
        const float l0 = slog[lane];
        const float l1 = slog[lane + 32];
        float m = fmaxf(l0, l1);
        #pragma unroll
        for (int o = 16; o > 0; o >>= 1)
            m = fmaxf(m, __shfl_xor_sync(0xffffffffu, m, o));
        float s = expf(l0 - m) + ((lane + 32 < NLOGITS) ? expf(l1 - m) : 0.0f);
        #pragma unroll
        for (int o = 16; o > 0; o >>= 1)
            s += __shfl_xor_sync(0xffffffffu, s, o);
        if (lane == 0) {
            g_row_loss[b] = logf(s) + m - slog[0];
            __threadfence();
            const int t = atomicAdd(&g_ctr, 1);
            s_last = (t == BN - 1);
        }
    }
    __syncthreads();

    // Last CTA: deterministic mean over all 4096 row losses.
    if (s_last) {
        __threadfence();
        __shared__ float sred[256];
        float acc = 0.0f;
        #pragma unroll
        for (int i = tid; i < BN; i += 256) acc += g_row_loss[i];
        sred[tid] = acc;
        __syncthreads();
        #pragma unroll
        for (int st = 128; st > 0; st >>= 1) {
            if (tid < st) sred[tid] += sred[tid + st];
            __syncthreads();
        }
        if (tid == 0) {
            out[0] = sred[0] * (1.0f / (float)BN);
            g_ctr = 0;                                 // reset for next graph replay
        }
    }
}

extern "C" void kernel_launch(void* const* d_in, const int* in_sizes, int n_in,
                              void* d_out, int out_size)
{
    const float* user_emb = (const float*)d_in[0];
    const float* item_emb = (const float*)d_in[1];
    const int*   neg_idx  = (const int*)d_in[2];
    float*       out      = (float*)d_out;

    quantize_rows_kernel<<<2 * BN / 8, 256>>>(item_emb, user_emb);
    u2i_loss_kernel<<<BN, 256>>>(neg_idx, out);
}

// round 13
// speedup vs baseline: 1.8563x; 1.2138x over previous
#include <cuda_runtime.h>

// Problem constants (fixed by the reference).
#define BN 4096
#define DN 768
#define KN 60
#define NLOGITS 61   // [pos, 60 negs]
#define NW 192       // int32 words per row (768 int8)
#define ROWS_PER_CTA 4
#define GRID (BN / ROWS_PER_CTA)   // 1024

// Scratch (__device__ globals: no allocation allowed).
__device__ __align__(256) int g_item_i8[BN * NW];   // 3 MB int8 item table
__device__ __align__(256) int g_user_i8[BN * NW];   // 3 MB int8 user table
__device__ float g_item_scale[BN];                  // per-row max/127
__device__ float g_user_scale[BN];
__device__ float g_row_loss[BN];
__device__ int   g_ctr = 0;

// ---------------------------------------------------------------------------
// Prologue: per-row symmetric int8 quantization of BOTH tables.
// One warp per row; gwarp < BN -> item row, else user row.
// ---------------------------------------------------------------------------
__global__ void __launch_bounds__(256)
quantize_rows_kernel(const float* __restrict__ item_emb,
                     const float* __restrict__ user_emb)
{
    const int gwarp = (blockIdx.x * 256 + threadIdx.x) >> 5;   // 0 .. 2*BN-1
    const int lane  = threadIdx.x & 31;

    const float* src;
    int*   dst;
    float* sc;
    if (gwarp < BN) {
        src = item_emb + (size_t)gwarp * DN;
        dst = g_item_i8 + (size_t)gwarp * NW;
        sc  = &g_item_scale[gwarp];
    } else {
        const int r = gwarp - BN;
        src = user_emb + (size_t)r * DN;
        dst = g_user_i8 + (size_t)r * NW;
        sc  = &g_user_scale[r];
    }

    const float4* s4 = reinterpret_cast<const float4*>(src);
    float4 v[6];
    float m = 0.0f;
    #pragma unroll
    for (int t = 0; t < 6; ++t) {
        v[t] = __ldg(&s4[t * 32 + lane]);
        m = fmaxf(m, fmaxf(fmaxf(fabsf(v[t].x), fabsf(v[t].y)),
                           fmaxf(fabsf(v[t].z), fabsf(v[t].w))));
    }
    #pragma unroll
    for (int o = 16; o > 0; o >>= 1)
        m = fmaxf(m, __shfl_xor_sync(0xffffffffu, m, o));
    m = fmaxf(m, 1e-20f);
    const float inv = 127.0f / m;

    #pragma unroll
    for (int t = 0; t < 6; ++t) {
        const int qx = __float2int_rn(v[t].x * inv);
        const int qy = __float2int_rn(v[t].y * inv);
        const int qz = __float2int_rn(v[t].z * inv);
        const int qw = __float2int_rn(v[t].w * inv);
        dst[t * 32 + lane] = (qx & 0xFF) | ((qy & 0xFF) << 8) |
                             ((qz & 0xFF) << 16) | (qw << 24);
    }
    if (lane == 0) *sc = m / 127.0f;
}

// ---------------------------------------------------------------------------
// Main: ONE WARP PER ROW. 4 warps/CTA, grid = 1024.
// 31 independent pair-iterations per warp (latency pipelines across them),
// int2 gathers (LDG.64), paired 6-shfl reductions, in-warp logsumexp.
// ---------------------------------------------------------------------------
__global__ void __launch_bounds__(128, 6)
u2i_loss_kernel(const int* __restrict__ neg_idx,
                float*     __restrict__ out)
{
    __shared__ int   s_idx[ROWS_PER_CTA * 64];
    __shared__ float s_scale[ROWS_PER_CTA * 64];
    __shared__ float slog[ROWS_PER_CTA * 64];
    __shared__ int   s_last;

    const int tid  = threadIdx.x;
    const int warp = tid >> 5;
    const int lane = tid & 31;
    const int row  = blockIdx.x * ROWS_PER_CTA + warp;
    const int base = warp * 64;

    // Per-warp prologue: 61 indices + scales into warp-private smem.
    if (lane < 30) {
        const int2 v = __ldg(reinterpret_cast<const int2*>(neg_idx + (size_t)row * KN + 2 * lane));
        s_idx[base + 1 + 2 * lane] = v.x;
        s_idx[base + 2 + 2 * lane] = v.y;
        s_scale[base + 1 + 2 * lane] = __ldg(&g_item_scale[v.x]);
        s_scale[base + 2 + 2 * lane] = __ldg(&g_item_scale[v.y]);
    } else if (lane == 30) {
        s_idx[base] = row;                             // logit 0 = positive
        s_scale[base] = __ldg(&g_item_scale[row]);
    } else {
        s_idx[base + 61] = 0; s_idx[base + 62] = 0; s_idx[base + 63] = 0;
        slog[base + 61] = -3.0e38f;
        slog[base + 62] = -3.0e38f;
        slog[base + 63] = -3.0e38f;
    }

    // User slice: 6 int32 words (3 x LDG.64) + scale.
    const int2* uq2 = reinterpret_cast<const int2*>(g_user_i8 + (size_t)row * NW);
    int u[6];
    #pragma unroll
    for (int t = 0; t < 3; ++t) {
        const int2 w = __ldg(&uq2[t * 32 + lane]);
        u[2 * t]     = w.x;
        u[2 * t + 1] = w.y;
    }
    const float su = __ldg(&g_user_scale[row]);
    __syncwarp();

    // 31 pair-iterations: logits (2p, 2p+1); p=30 pairs (60, dummy).
    #pragma unroll
    for (int p = 0; p < 31; ++p) {
        const int jA = 2 * p;
        const int jB = 2 * p + 1;
        const int iA = s_idx[base + jA];
        const int iB = s_idx[base + jB];

        const int2* pA = reinterpret_cast<const int2*>(g_item_i8 + (size_t)iA * NW);
        const int2* pB = reinterpret_cast<const int2*>(g_item_i8 + (size_t)iB * NW);

        const int2 a0 = __ldg(&pA[lane]);
        const int2 a1 = __ldg(&pA[32 + lane]);
        const int2 a2 = __ldg(&pA[64 + lane]);
        const int2 b0 = __ldg(&pB[lane]);
        const int2 b1 = __ldg(&pB[32 + lane]);
        const int2 b2 = __ldg(&pB[64 + lane]);

        int accA = 0, accB = 0;
        accA = __dp4a(a0.x, u[0], accA);
        accA = __dp4a(a0.y, u[1], accA);
        accA = __dp4a(a1.x, u[2], accA);
        accA = __dp4a(a1.y, u[3], accA);
        accA = __dp4a(a2.x, u[4], accA);
        accA = __dp4a(a2.y, u[5], accA);
        accB = __dp4a(b0.x, u[0], accB);
        accB = __dp4a(b0.y, u[1], accB);
        accB = __dp4a(b1.x, u[2], accB);
        accB = __dp4a(b1.y, u[3], accB);
        accB = __dp4a(b2.x, u[4], accB);
        accB = __dp4a(b2.y, u[5], accB);

        // Paired reduction: 6 shfls for both exact int sums.
        accA += __shfl_xor_sync(0xffffffffu, accA, 16);
        accB += __shfl_xor_sync(0xffffffffu, accB, 16);
        int v = (lane < 16) ? accA : accB;
        #pragma unroll
        for (int o = 8; o > 0; o >>= 1)
            v += __shfl_xor_sync(0xffffffffu, v, o);

        if (lane == 0)               slog[base + jA] = (float)v * su * s_scale[base + jA];
        if (lane == 16 && jB < NLOGITS) slog[base + jB] = (float)v * su * s_scale[base + jB];
    }
    __syncwarp();

    // In-warp stable logsumexp over 61 logits (2 per lane; 62..63 = -inf).
    {
        const float l0 = slog[base + lane];
        const float l1 = slog[base + lane + 32];
        float m = fmaxf(l0, l1);
        #pragma unroll
        for (int o = 16; o > 0; o >>= 1)
            m = fmaxf(m, __shfl_xor_sync(0xffffffffu, m, o));
        float s = expf(l0 - m) + ((lane + 32 < NLOGITS) ? expf(l1 - m) : 0.0f);
        #pragma unroll
        for (int o = 16; o > 0; o >>= 1)
            s += __shfl_xor_sync(0xffffffffu, s, o);
        if (lane == 0) {
            g_row_loss[row] = logf(s) + m - slog[base];
            __threadfence();                            // release this row's loss
        }
    }
    __syncthreads();

    // CTA ticket; the last CTA performs the deterministic mean.
    if (tid == 0) {
        __threadfence();
        const int t = atomicAdd(&g_ctr, 1);
        s_last = (t == GRID - 1);
    }
    __syncthreads();

    if (s_last) {
        __threadfence();
        __shared__ float sred[128];
        float a = 0.0f;
        #pragma unroll
        for (int i = tid; i < BN; i += 128) a += g_row_loss[i];
        sred[tid] = a;
        __syncthreads();
        #pragma unroll
        for (int st = 64; st > 0; st >>= 1) {
            if (tid < st) sred[tid] += sred[tid + st];
            __syncthreads();
        }
        if (tid == 0) {
            out[0] = sred[0] * (1.0f / (float)BN);
            g_ctr = 0;                                 // reset for next graph replay
        }
    }
}

extern "C" void kernel_launch(void* const* d_in, const int* in_sizes, int n_in,
                              void* d_out, int out_size)
{
    const float* user_emb = (const float*)d_in[0];
    const float* item_emb = (const float*)d_in[1];
    const int*   neg_idx  = (const int*)d_in[2];
    float*       out      = (float*)d_out;

    quantize_rows_kernel<<<2 * BN / 8, 256>>>(item_emb, user_emb);
    u2i_loss_kernel<<<GRID, 128>>>(neg_idx, out);
}